// round 14
// baseline (speedup 1.0000x reference)
#include <cuda_runtime.h>
#include <cuda_bf16.h>
#include <cstdint>

// ---------------- problem dims (fixed by setup_inputs) ----------------
#define DIN   4096
#define DOUT  4096
#define TMAX  8192

// ---------------- scratch (device globals: alloc-free rule) -----------
__device__ __align__(1024) unsigned short g_q[(size_t)TMAX * DIN];   // 64 MB bf16 q (exact ints)
__device__ __align__(1024) unsigned short g_w2[2ull * DOUT * DIN];   // 64 MB bf16 W_hi | W_lo
__device__ float g_ts[TMAX];                                         // per-token scale

// ============================================================================
// Kernel 1: 2:4 activation sparsity + per-token absmax quant -> q (bf16), scale
// ============================================================================
__global__ void __launch_bounds__(128) prep_kernel(const float* __restrict__ x,
                                                   const float* __restrict__ ss) {
    int t = blockIdx.x;
    int tid = threadIdx.x;
    const float4* xr = reinterpret_cast<const float4*>(x + (size_t)t * DIN);
    const float4* sr = reinterpret_cast<const float4*>(ss);

    float4 v[8];
    float amax = 0.f;
#pragma unroll
    for (int j = 0; j < 8; ++j) {
        int g = tid + j * 128;                 // one group of 4 columns
        float4 xv = xr[g];
        float4 sv = __ldg(sr + g);
        float a0 = fabsf(xv.x) * sv.x;
        float a1 = fabsf(xv.y) * sv.y;
        float a2 = fabsf(xv.z) * sv.z;
        float a3 = fabsf(xv.w) * sv.w;
        // rank(j) = #{i : m_i < m_j or (m_i == m_j and i < j)}; zero if rank < 2
        // (matches jax.lax.top_k stable tie-break: lower index picked as "smaller")
        int r0 = (a1 <  a0) + (a2 <  a0) + (a3 <  a0);
        int r1 = (a0 <= a1) + (a2 <  a1) + (a3 <  a1);
        int r2 = (a0 <= a2) + (a1 <= a2) + (a3 <  a2);
        int r3 = (a0 <= a3) + (a1 <= a3) + (a2 <= a3);
        xv.x = (r0 >= 2) ? xv.x : 0.f;
        xv.y = (r1 >= 2) ? xv.y : 0.f;
        xv.z = (r2 >= 2) ? xv.z : 0.f;
        xv.w = (r3 >= 2) ? xv.w : 0.f;
        v[j] = xv;
        amax = fmaxf(amax, fmaxf(fmaxf(fabsf(xv.x), fabsf(xv.y)),
                                 fmaxf(fabsf(xv.z), fabsf(xv.w))));
    }
#pragma unroll
    for (int o = 16; o > 0; o >>= 1)
        amax = fmaxf(amax, __shfl_xor_sync(0xffffffffu, amax, o));
    __shared__ float red[4];
    if ((tid & 31) == 0) red[tid >> 5] = amax;
    __syncthreads();
    float am = fmaxf(fmaxf(red[0], red[1]), fmaxf(red[2], red[3]));
    float s = fmaxf(am, 1e-5f) / 127.0f;       // same op order as reference
    if (tid == 0) g_ts[t] = s;

    ushort4* qr = reinterpret_cast<ushort4*>(g_q + (size_t)t * DIN);
#pragma unroll
    for (int j = 0; j < 8; ++j) {
        int g = tid + j * 128;
        float4 xv = v[j];
        ushort4 u;  // q integers, |q|<=127 -> exact in bf16
        u.x = __bfloat16_as_ushort(__float2bfloat16(rintf(__fdiv_rn(xv.x, s))));
        u.y = __bfloat16_as_ushort(__float2bfloat16(rintf(__fdiv_rn(xv.y, s))));
        u.z = __bfloat16_as_ushort(__float2bfloat16(rintf(__fdiv_rn(xv.z, s))));
        u.w = __bfloat16_as_ushort(__float2bfloat16(rintf(__fdiv_rn(xv.w, s))));
        qr[g] = u;
    }
}

// ============================================================================
// Kernel 2: split fp32 W into bf16 hi + lo planes (W ~= hi + lo, ~2^-17 rel)
// ============================================================================
__global__ void __launch_bounds__(256) wsplit_kernel(const float* __restrict__ w) {
    int i = blockIdx.x * 256 + threadIdx.x;   // float4 index over DOUT*DIN/4
    float4 wv = reinterpret_cast<const float4*>(w)[i];
    __nv_bfloat16 h0 = __float2bfloat16(wv.x);
    __nv_bfloat16 h1 = __float2bfloat16(wv.y);
    __nv_bfloat16 h2 = __float2bfloat16(wv.z);
    __nv_bfloat16 h3 = __float2bfloat16(wv.w);
    __nv_bfloat16 l0 = __float2bfloat16(wv.x - __bfloat162float(h0));
    __nv_bfloat16 l1 = __float2bfloat16(wv.y - __bfloat162float(h1));
    __nv_bfloat16 l2 = __float2bfloat16(wv.z - __bfloat162float(h2));
    __nv_bfloat16 l3 = __float2bfloat16(wv.w - __bfloat162float(h3));
    ushort4 uh, ul;
    uh.x = __bfloat16_as_ushort(h0); uh.y = __bfloat16_as_ushort(h1);
    uh.z = __bfloat16_as_ushort(h2); uh.w = __bfloat16_as_ushort(h3);
    ul.x = __bfloat16_as_ushort(l0); ul.y = __bfloat16_as_ushort(l1);
    ul.z = __bfloat16_as_ushort(l2); ul.w = __bfloat16_as_ushort(l3);
    reinterpret_cast<ushort4*>(g_w2)[i] = uh;
    reinterpret_cast<ushort4*>(g_w2)[i + ((size_t)DOUT * DIN) / 4] = ul;
}

// ============================================================================
// Kernel 3: pipelined HMMA GEMM (sm_103 non-"a" PTX only: cp.async + ldmatrix
//           + mma.sync.m16n8k16.bf16).  out[m][n] = ts[m]*sum_k q*(Whi+Wlo) + bias
// CTA tile 128x128, BK=64, 4 cp.async stages (48KB/stage), 8 warps 2(M)x4(N),
// warp tile 64x32, both W planes accumulated into the same fp32 registers.
// ============================================================================
#define BK        64
#define KITERS    (DIN / BK)
#define STAGES    4
#define STAGE_B   49152                 // 16KB A + 2*16KB B
#define SMEM_BYTES (STAGES * STAGE_B)
#define PLANE     ((size_t)DOUT * DIN)

__device__ __forceinline__ uint32_t smem_u32(const void* p) {
    uint32_t a;
    asm("{ .reg .u64 t; cvta.to.shared.u64 t, %1; cvt.u32.u64 %0, t; }" : "=r"(a) : "l"(p));
    return a;
}
__device__ __forceinline__ void cp16(uint32_t dst, const void* src) {
    asm volatile("cp.async.cg.shared.global [%0], [%1], 16;" :: "r"(dst), "l"(src));
}
#define CP_COMMIT() asm volatile("cp.async.commit_group;" ::: "memory")
#define CP_WAIT2()  asm volatile("cp.async.wait_group 2;" ::: "memory")

#define LDSM4(r, addr) \
    asm volatile("ldmatrix.sync.aligned.m8n8.x4.shared.b16 {%0,%1,%2,%3}, [%4];" \
        : "=r"((r)[0]), "=r"((r)[1]), "=r"((r)[2]), "=r"((r)[3]) : "r"(addr))

#define MMA16816(d, a, b0, b1) \
    asm volatile("mma.sync.aligned.m16n8k16.row.col.f32.bf16.bf16.f32 " \
        "{%0,%1,%2,%3}, {%4,%5,%6,%7}, {%8,%9}, {%0,%1,%2,%3};" \
        : "+f"((d)[0]), "+f"((d)[1]), "+f"((d)[2]), "+f"((d)[3]) \
        : "r"((a)[0]), "r"((a)[1]), "r"((a)[2]), "r"((a)[3]), "r"(b0), "r"(b1))

__global__ void __launch_bounds__(256, 1) gemm_kernel(const float* __restrict__ bias,
                                                      float* __restrict__ out) {
    extern __shared__ __align__(1024) char smem[];
    const uint32_t sb = smem_u32(smem);
    const int tid  = threadIdx.x;
    const int lane = tid & 31;
    const int wid  = tid >> 5;
    const int wm   = wid & 1;            // 2 warps along M
    const int wn   = wid >> 1;           // 4 warps along N
    const int m0   = blockIdx.y * 128;
    const int n0   = blockIdx.x * 128;

    // ---------- cp.async producer addressing (per thread: 12 x 16B) ----------
    // chunk layout: 128 rows x 8 chunks (16B) per 64-col bf16 row; 8-row XOR swizzle
    const int prow = tid >> 3;           // 0..31, +t*32
    const int pcol = tid & 7;
    const uint32_t dst0 = (uint32_t)prow * 128 + (uint32_t)((pcol ^ (prow & 7)) << 4);
    const unsigned short* qa = g_q  + (size_t)(m0 + prow) * DIN + pcol * 8;
    const unsigned short* wb = g_w2 + (size_t)(n0 + prow) * DIN + pcol * 8;

    // ---------- ldmatrix consumer addressing ----------
    const uint32_t sw   = (uint32_t)(lane & 7);
    const uint32_t ahi  = (uint32_t)((lane >> 4) & 1);       // A k-chunk half
    const uint32_t bkb  = (uint32_t)((lane >> 3) & 1);       // B k-chunk half
    uint32_t rA[4], rB[2];
#pragma unroll
    for (int mt = 0; mt < 4; ++mt)
        rA[mt] = (uint32_t)(wm * 64 + mt * 16 + (lane & 15)) * 128;
#pragma unroll
    for (int ntp = 0; ntp < 2; ++ntp)
        rB[ntp] = (uint32_t)(wn * 32 + ntp * 16 + ((lane >> 4) & 1) * 8 + (lane & 7)) * 128;

    float acc[4][4][4];
#pragma unroll
    for (int i = 0; i < 4; ++i)
#pragma unroll
        for (int j = 0; j < 4; ++j)
#pragma unroll
            for (int k = 0; k < 4; ++k) acc[i][j][k] = 0.f;

    // ---------- prologue: fill STAGES-1 stages ----------
#pragma unroll
    for (int s = 0; s < STAGES - 1; ++s) {
        uint32_t sbase = sb + s * STAGE_B;
        int koff = s * BK;
#pragma unroll
        for (int t = 0; t < 4; ++t) {
            cp16(sbase +         dst0 + t * 4096, qa + (size_t)t * 32 * DIN + koff);
            cp16(sbase + 16384 + dst0 + t * 4096, wb + (size_t)t * 32 * DIN + koff);
            cp16(sbase + 32768 + dst0 + t * 4096, wb + PLANE + (size_t)t * 32 * DIN + koff);
        }
        CP_COMMIT();
    }

    // ---------- main loop ----------
#pragma unroll 1
    for (int kt = 0; kt < KITERS; ++kt) {
        CP_WAIT2();
        __syncthreads();

        const uint32_t stA = sb + (kt % STAGES) * STAGE_B;
#pragma unroll
        for (int ks = 0; ks < 4; ++ks) {
            uint32_t a[4][4];
#pragma unroll
            for (int mt = 0; mt < 4; ++mt) {
                uint32_t addr = stA + rA[mt] + (((2u * ks + ahi) ^ sw) << 4);
                LDSM4(a[mt], addr);
            }
#pragma unroll
            for (int p = 0; p < 2; ++p) {
                uint32_t pb = stA + 16384 + p * 16384;
#pragma unroll
                for (int ntp = 0; ntp < 2; ++ntp) {
                    uint32_t b[4];
                    uint32_t addr = pb + rB[ntp] + (((2u * ks + bkb) ^ sw) << 4);
                    LDSM4(b, addr);
#pragma unroll
                    for (int mt = 0; mt < 4; ++mt) {
                        MMA16816(acc[mt][2 * ntp],     a[mt], b[0], b[1]);
                        MMA16816(acc[mt][2 * ntp + 1], a[mt], b[2], b[3]);
                    }
                }
            }
        }
        __syncthreads();

        int nk = kt + STAGES - 1;
        if (nk < KITERS) {
            uint32_t sbase = sb + (nk % STAGES) * STAGE_B;
            int koff = nk * BK;
#pragma unroll
            for (int t = 0; t < 4; ++t) {
                cp16(sbase +         dst0 + t * 4096, qa + (size_t)t * 32 * DIN + koff);
                cp16(sbase + 16384 + dst0 + t * 4096, wb + (size_t)t * 32 * DIN + koff);
                cp16(sbase + 32768 + dst0 + t * 4096, wb + PLANE + (size_t)t * 32 * DIN + koff);
            }
        }
        CP_COMMIT();
    }

    // ---------- epilogue: y = acc * ts[m] + bias[n] ----------
    const int mbase = m0 + wm * 64;
    const int nbase = n0 + wn * 32;
#pragma unroll
    for (int mt = 0; mt < 4; ++mt) {
        int r = mbase + mt * 16 + (lane >> 2);
        float s0 = g_ts[r];
        float s1 = g_ts[r + 8];
        float* o0 = out + (size_t)r * DOUT;
        float* o1 = o0 + (size_t)8 * DOUT;
#pragma unroll
        for (int nt = 0; nt < 4; ++nt) {
            int n = nbase + nt * 8 + (lane & 3) * 2;
            float2 bb = *reinterpret_cast<const float2*>(bias + n);
            float2 v0, v1;
            v0.x = acc[mt][nt][0] * s0 + bb.x;
            v0.y = acc[mt][nt][1] * s0 + bb.y;
            v1.x = acc[mt][nt][2] * s1 + bb.x;
            v1.y = acc[mt][nt][3] * s1 + bb.y;
            *reinterpret_cast<float2*>(o0 + n) = v0;
            *reinterpret_cast<float2*>(o1 + n) = v1;
        }
    }
}

// ============================================================================
// host launcher
// ============================================================================
extern "C" void kernel_launch(void* const* d_in, const int* in_sizes, int n_in,
                              void* d_out, int out_size) {
    const float* x    = (const float*)d_in[0];   // (B,S,DIN)
    const float* w    = (const float*)d_in[1];   // (DOUT,DIN)
    const float* bias = (const float*)d_in[2];   // (1,DOUT)
    const float* ss   = (const float*)d_in[3];   // (1,DIN)
    float* out = (float*)d_out;
    int T = in_sizes[0] / DIN;                   // 8192 tokens

    static bool attr_set = false;
    if (!attr_set) {
        cudaFuncSetAttribute(gemm_kernel, cudaFuncAttributeMaxDynamicSharedMemorySize,
                             SMEM_BYTES);
        attr_set = true;
    }

    prep_kernel<<<T, 128>>>(x, ss);
    wsplit_kernel<<<(DOUT * DIN / 4) / 256, 256>>>(w);
    dim3 grid(DOUT / 128, T / 128);
    gemm_kernel<<<grid, 256, SMEM_BYTES>>>(bias, out);
}

// round 15
// speedup vs baseline: 1.0001x; 1.0001x over previous
#include <cuda_runtime.h>
#include <cuda_bf16.h>
#include <cstdint>

// ---------------- problem dims (fixed by setup_inputs) ----------------
#define DIN   4096
#define DOUT  4096
#define TMAX  8192

// ---------------- scratch (device globals: alloc-free rule) -----------
__device__ __align__(1024) unsigned short g_q[(size_t)TMAX * DIN];   // 64 MB bf16 q (exact ints)
__device__ __align__(1024) unsigned short g_w2[2ull * DOUT * DIN];   // 64 MB bf16 W_hi | W_lo
__device__ float g_ts[TMAX];                                         // per-token scale

// ============================================================================
// Kernel 1: 2:4 activation sparsity + per-token absmax quant -> q (bf16), scale
// ============================================================================
__global__ void __launch_bounds__(128) prep_kernel(const float* __restrict__ x,
                                                   const float* __restrict__ ss) {
    int t = blockIdx.x;
    int tid = threadIdx.x;
    const float4* xr = reinterpret_cast<const float4*>(x + (size_t)t * DIN);
    const float4* sr = reinterpret_cast<const float4*>(ss);

    float4 v[8];
    float amax = 0.f;
#pragma unroll
    for (int j = 0; j < 8; ++j) {
        int g = tid + j * 128;                 // one group of 4 columns
        float4 xv = xr[g];
        float4 sv = __ldg(sr + g);
        float a0 = fabsf(xv.x) * sv.x;
        float a1 = fabsf(xv.y) * sv.y;
        float a2 = fabsf(xv.z) * sv.z;
        float a3 = fabsf(xv.w) * sv.w;
        // rank(j) = #{i : m_i < m_j or (m_i == m_j and i < j)}; zero if rank < 2
        // (matches jax.lax.top_k stable tie-break: lower index picked as "smaller")
        int r0 = (a1 <  a0) + (a2 <  a0) + (a3 <  a0);
        int r1 = (a0 <= a1) + (a2 <  a1) + (a3 <  a1);
        int r2 = (a0 <= a2) + (a1 <= a2) + (a3 <  a2);
        int r3 = (a0 <= a3) + (a1 <= a3) + (a2 <= a3);
        xv.x = (r0 >= 2) ? xv.x : 0.f;
        xv.y = (r1 >= 2) ? xv.y : 0.f;
        xv.z = (r2 >= 2) ? xv.z : 0.f;
        xv.w = (r3 >= 2) ? xv.w : 0.f;
        v[j] = xv;
        amax = fmaxf(amax, fmaxf(fmaxf(fabsf(xv.x), fabsf(xv.y)),
                                 fmaxf(fabsf(xv.z), fabsf(xv.w))));
    }
#pragma unroll
    for (int o = 16; o > 0; o >>= 1)
        amax = fmaxf(amax, __shfl_xor_sync(0xffffffffu, amax, o));
    __shared__ float red[4];
    if ((tid & 31) == 0) red[tid >> 5] = amax;
    __syncthreads();
    float am = fmaxf(fmaxf(red[0], red[1]), fmaxf(red[2], red[3]));
    float s = fmaxf(am, 1e-5f) / 127.0f;       // same op order as reference
    if (tid == 0) g_ts[t] = s;

    ushort4* qr = reinterpret_cast<ushort4*>(g_q + (size_t)t * DIN);
#pragma unroll
    for (int j = 0; j < 8; ++j) {
        int g = tid + j * 128;
        float4 xv = v[j];
        ushort4 u;  // q integers, |q|<=127 -> exact in bf16
        u.x = __bfloat16_as_ushort(__float2bfloat16(rintf(__fdiv_rn(xv.x, s))));
        u.y = __bfloat16_as_ushort(__float2bfloat16(rintf(__fdiv_rn(xv.y, s))));
        u.z = __bfloat16_as_ushort(__float2bfloat16(rintf(__fdiv_rn(xv.z, s))));
        u.w = __bfloat16_as_ushort(__float2bfloat16(rintf(__fdiv_rn(xv.w, s))));
        qr[g] = u;
    }
}

// ============================================================================
// Kernel 2: split fp32 W into bf16 hi + lo planes (W ~= hi + lo, ~2^-17 rel)
// ============================================================================
__global__ void __launch_bounds__(256) wsplit_kernel(const float* __restrict__ w) {
    int i = blockIdx.x * 256 + threadIdx.x;   // float4 index over DOUT*DIN/4
    float4 wv = reinterpret_cast<const float4*>(w)[i];
    __nv_bfloat16 h0 = __float2bfloat16(wv.x);
    __nv_bfloat16 h1 = __float2bfloat16(wv.y);
    __nv_bfloat16 h2 = __float2bfloat16(wv.z);
    __nv_bfloat16 h3 = __float2bfloat16(wv.w);
    __nv_bfloat16 l0 = __float2bfloat16(wv.x - __bfloat162float(h0));
    __nv_bfloat16 l1 = __float2bfloat16(wv.y - __bfloat162float(h1));
    __nv_bfloat16 l2 = __float2bfloat16(wv.z - __bfloat162float(h2));
    __nv_bfloat16 l3 = __float2bfloat16(wv.w - __bfloat162float(h3));
    ushort4 uh, ul;
    uh.x = __bfloat16_as_ushort(h0); uh.y = __bfloat16_as_ushort(h1);
    uh.z = __bfloat16_as_ushort(h2); uh.w = __bfloat16_as_ushort(h3);
    ul.x = __bfloat16_as_ushort(l0); ul.y = __bfloat16_as_ushort(l1);
    ul.z = __bfloat16_as_ushort(l2); ul.w = __bfloat16_as_ushort(l3);
    reinterpret_cast<ushort4*>(g_w2)[i] = uh;
    reinterpret_cast<ushort4*>(g_w2)[i + ((size_t)DOUT * DIN) / 4] = ul;
}

// ============================================================================
// Kernel 3: pipelined HMMA GEMM (sm_103 non-"a" PTX only: cp.async + ldmatrix
//           + mma.sync.m16n8k16.bf16).  out[m][n] = ts[m]*sum_k q*(Whi+Wlo) + bias
// CTA tile 128x128, BK=64, 4 cp.async stages (48KB/stage), 8 warps 2(M)x4(N),
// warp tile 64x32, both W planes accumulated into the same fp32 registers.
// ============================================================================
#define BK        64
#define KITERS    (DIN / BK)
#define STAGES    4
#define STAGE_B   49152                 // 16KB A + 2*16KB B
#define SMEM_BYTES (STAGES * STAGE_B)
#define PLANE     ((size_t)DOUT * DIN)

__device__ __forceinline__ uint32_t smem_u32(const void* p) {
    uint32_t a;
    asm("{ .reg .u64 t; cvta.to.shared.u64 t, %1; cvt.u32.u64 %0, t; }" : "=r"(a) : "l"(p));
    return a;
}
__device__ __forceinline__ void cp16(uint32_t dst, const void* src) {
    asm volatile("cp.async.cg.shared.global [%0], [%1], 16;" :: "r"(dst), "l"(src));
}
#define CP_COMMIT() asm volatile("cp.async.commit_group;" ::: "memory")
#define CP_WAIT2()  asm volatile("cp.async.wait_group 2;" ::: "memory")

#define LDSM4(r, addr) \
    asm volatile("ldmatrix.sync.aligned.m8n8.x4.shared.b16 {%0,%1,%2,%3}, [%4];" \
        : "=r"((r)[0]), "=r"((r)[1]), "=r"((r)[2]), "=r"((r)[3]) : "r"(addr))

#define MMA16816(d, a, b0, b1) \
    asm volatile("mma.sync.aligned.m16n8k16.row.col.f32.bf16.bf16.f32 " \
        "{%0,%1,%2,%3}, {%4,%5,%6,%7}, {%8,%9}, {%0,%1,%2,%3};" \
        : "+f"((d)[0]), "+f"((d)[1]), "+f"((d)[2]), "+f"((d)[3]) \
        : "r"((a)[0]), "r"((a)[1]), "r"((a)[2]), "r"((a)[3]), "r"(b0), "r"(b1))

__global__ void __launch_bounds__(256, 1) gemm_kernel(const float* __restrict__ bias,
                                                      float* __restrict__ out) {
    extern __shared__ __align__(1024) char smem[];
    const uint32_t sb = smem_u32(smem);
    const int tid  = threadIdx.x;
    const int lane = tid & 31;
    const int wid  = tid >> 5;
    const int wm   = wid & 1;            // 2 warps along M
    const int wn   = wid >> 1;           // 4 warps along N
    const int m0   = blockIdx.y * 128;
    const int n0   = blockIdx.x * 128;

    // ---------- cp.async producer addressing (per thread: 12 x 16B) ----------
    // chunk layout: 128 rows x 8 chunks (16B) per 64-col bf16 row; 8-row XOR swizzle
    const int prow = tid >> 3;           // 0..31, +t*32
    const int pcol = tid & 7;
    const uint32_t dst0 = (uint32_t)prow * 128 + (uint32_t)((pcol ^ (prow & 7)) << 4);
    const unsigned short* qa = g_q  + (size_t)(m0 + prow) * DIN + pcol * 8;
    const unsigned short* wb = g_w2 + (size_t)(n0 + prow) * DIN + pcol * 8;

    // ---------- ldmatrix consumer addressing ----------
    const uint32_t sw   = (uint32_t)(lane & 7);
    const uint32_t ahi  = (uint32_t)((lane >> 4) & 1);       // A k-chunk half
    const uint32_t bkb  = (uint32_t)((lane >> 3) & 1);       // B k-chunk half
    uint32_t rA[4], rB[2];
#pragma unroll
    for (int mt = 0; mt < 4; ++mt)
        rA[mt] = (uint32_t)(wm * 64 + mt * 16 + (lane & 15)) * 128;
#pragma unroll
    for (int ntp = 0; ntp < 2; ++ntp)
        rB[ntp] = (uint32_t)(wn * 32 + ntp * 16 + ((lane >> 4) & 1) * 8 + (lane & 7)) * 128;

    float acc[4][4][4];
#pragma unroll
    for (int i = 0; i < 4; ++i)
#pragma unroll
        for (int j = 0; j < 4; ++j)
#pragma unroll
            for (int k = 0; k < 4; ++k) acc[i][j][k] = 0.f;

    // ---------- prologue: fill STAGES-1 stages ----------
#pragma unroll
    for (int s = 0; s < STAGES - 1; ++s) {
        uint32_t sbase = sb + s * STAGE_B;
        int koff = s * BK;
#pragma unroll
        for (int t = 0; t < 4; ++t) {
            cp16(sbase +         dst0 + t * 4096, qa + (size_t)t * 32 * DIN + koff);
            cp16(sbase + 16384 + dst0 + t * 4096, wb + (size_t)t * 32 * DIN + koff);
            cp16(sbase + 32768 + dst0 + t * 4096, wb + PLANE + (size_t)t * 32 * DIN + koff);
        }
        CP_COMMIT();
    }

    // ---------- main loop ----------
#pragma unroll 1
    for (int kt = 0; kt < KITERS; ++kt) {
        CP_WAIT2();
        __syncthreads();

        const uint32_t stA = sb + (kt % STAGES) * STAGE_B;
#pragma unroll
        for (int ks = 0; ks < 4; ++ks) {
            uint32_t a[4][4];
#pragma unroll
            for (int mt = 0; mt < 4; ++mt) {
                uint32_t addr = stA + rA[mt] + (((2u * ks + ahi) ^ sw) << 4);
                LDSM4(a[mt], addr);
            }
#pragma unroll
            for (int p = 0; p < 2; ++p) {
                uint32_t pb = stA + 16384 + p * 16384;
#pragma unroll
                for (int ntp = 0; ntp < 2; ++ntp) {
                    uint32_t b[4];
                    uint32_t addr = pb + rB[ntp] + (((2u * ks + bkb) ^ sw) << 4);
                    LDSM4(b, addr);
#pragma unroll
                    for (int mt = 0; mt < 4; ++mt) {
                        MMA16816(acc[mt][2 * ntp],     a[mt], b[0], b[1]);
                        MMA16816(acc[mt][2 * ntp + 1], a[mt], b[2], b[3]);
                    }
                }
            }
        }
        __syncthreads();

        int nk = kt + STAGES - 1;
        if (nk < KITERS) {
            uint32_t sbase = sb + (nk % STAGES) * STAGE_B;
            int koff = nk * BK;
#pragma unroll
            for (int t = 0; t < 4; ++t) {
                cp16(sbase +         dst0 + t * 4096, qa + (size_t)t * 32 * DIN + koff);
                cp16(sbase + 16384 + dst0 + t * 4096, wb + (size_t)t * 32 * DIN + koff);
                cp16(sbase + 32768 + dst0 + t * 4096, wb + PLANE + (size_t)t * 32 * DIN + koff);
            }
        }
        CP_COMMIT();
    }

    // ---------- epilogue: y = acc * ts[m] + bias[n] ----------
    const int mbase = m0 + wm * 64;
    const int nbase = n0 + wn * 32;
#pragma unroll
    for (int mt = 0; mt < 4; ++mt) {
        int r = mbase + mt * 16 + (lane >> 2);
        float s0 = g_ts[r];
        float s1 = g_ts[r + 8];
        float* o0 = out + (size_t)r * DOUT;
        float* o1 = o0 + (size_t)8 * DOUT;
#pragma unroll
        for (int nt = 0; nt < 4; ++nt) {
            int n = nbase + nt * 8 + (lane & 3) * 2;
            float2 bb = *reinterpret_cast<const float2*>(bias + n);
            float2 v0, v1;
            v0.x = acc[mt][nt][0] * s0 + bb.x;
            v0.y = acc[mt][nt][1] * s0 + bb.y;
            v1.x = acc[mt][nt][2] * s1 + bb.x;
            v1.y = acc[mt][nt][3] * s1 + bb.y;
            *reinterpret_cast<float2*>(o0 + n) = v0;
            *reinterpret_cast<float2*>(o1 + n) = v1;
        }
    }
}

// ============================================================================
// host launcher
// ============================================================================
extern "C" void kernel_launch(void* const* d_in, const int* in_sizes, int n_in,
                              void* d_out, int out_size) {
    const float* x    = (const float*)d_in[0];   // (B,S,DIN)
    const float* w    = (const float*)d_in[1];   // (DOUT,DIN)
    const float* bias = (const float*)d_in[2];   // (1,DOUT)
    const float* ss   = (const float*)d_in[3];   // (1,DIN)
    float* out = (float*)d_out;
    int T = in_sizes[0] / DIN;                   // 8192 tokens

    static bool attr_set = false;
    if (!attr_set) {
        cudaFuncSetAttribute(gemm_kernel, cudaFuncAttributeMaxDynamicSharedMemorySize,
                             SMEM_BYTES);
        attr_set = true;
    }

    prep_kernel<<<T, 128>>>(x, ss);
    wsplit_kernel<<<(DOUT * DIN / 4) / 256, 256>>>(w);
    dim3 grid(DOUT / 128, T / 128);
    gemm_kernel<<<grid, 256, SMEM_BYTES>>>(bias, out);
}

// round 16
// speedup vs baseline: 1.0005x; 1.0005x over previous
#include <cuda_runtime.h>
#include <cuda_bf16.h>
#include <cstdint>

// ---------------- problem dims (fixed by setup_inputs) ----------------
#define DIN   4096
#define DOUT  4096
#define TMAX  8192

// ---------------- scratch (device globals: alloc-free rule) -----------
__device__ __align__(1024) unsigned short g_q[(size_t)TMAX * DIN];   // 64 MB bf16 q (exact ints)
__device__ __align__(1024) unsigned short g_w2[2ull * DOUT * DIN];   // 64 MB bf16 W_hi | W_lo
__device__ float g_ts[TMAX];                                         // per-token scale

// ============================================================================
// Kernel 1: 2:4 activation sparsity + per-token absmax quant -> q (bf16), scale
// ============================================================================
__global__ void __launch_bounds__(128) prep_kernel(const float* __restrict__ x,
                                                   const float* __restrict__ ss) {
    int t = blockIdx.x;
    int tid = threadIdx.x;
    const float4* xr = reinterpret_cast<const float4*>(x + (size_t)t * DIN);
    const float4* sr = reinterpret_cast<const float4*>(ss);

    float4 v[8];
    float amax = 0.f;
#pragma unroll
    for (int j = 0; j < 8; ++j) {
        int g = tid + j * 128;                 // one group of 4 columns
        float4 xv = xr[g];
        float4 sv = __ldg(sr + g);
        float a0 = fabsf(xv.x) * sv.x;
        float a1 = fabsf(xv.y) * sv.y;
        float a2 = fabsf(xv.z) * sv.z;
        float a3 = fabsf(xv.w) * sv.w;
        // rank(j) = #{i : m_i < m_j or (m_i == m_j and i < j)}; zero if rank < 2
        // (matches jax.lax.top_k stable tie-break: lower index picked as "smaller")
        int r0 = (a1 <  a0) + (a2 <  a0) + (a3 <  a0);
        int r1 = (a0 <= a1) + (a2 <  a1) + (a3 <  a1);
        int r2 = (a0 <= a2) + (a1 <= a2) + (a3 <  a2);
        int r3 = (a0 <= a3) + (a1 <= a3) + (a2 <= a3);
        xv.x = (r0 >= 2) ? xv.x : 0.f;
        xv.y = (r1 >= 2) ? xv.y : 0.f;
        xv.z = (r2 >= 2) ? xv.z : 0.f;
        xv.w = (r3 >= 2) ? xv.w : 0.f;
        v[j] = xv;
        amax = fmaxf(amax, fmaxf(fmaxf(fabsf(xv.x), fabsf(xv.y)),
                                 fmaxf(fabsf(xv.z), fabsf(xv.w))));
    }
#pragma unroll
    for (int o = 16; o > 0; o >>= 1)
        amax = fmaxf(amax, __shfl_xor_sync(0xffffffffu, amax, o));
    __shared__ float red[4];
    if ((tid & 31) == 0) red[tid >> 5] = amax;
    __syncthreads();
    float am = fmaxf(fmaxf(red[0], red[1]), fmaxf(red[2], red[3]));
    float s = fmaxf(am, 1e-5f) / 127.0f;       // same op order as reference
    if (tid == 0) g_ts[t] = s;

    ushort4* qr = reinterpret_cast<ushort4*>(g_q + (size_t)t * DIN);
#pragma unroll
    for (int j = 0; j < 8; ++j) {
        int g = tid + j * 128;
        float4 xv = v[j];
        ushort4 u;  // q integers, |q|<=127 -> exact in bf16
        u.x = __bfloat16_as_ushort(__float2bfloat16(rintf(__fdiv_rn(xv.x, s))));
        u.y = __bfloat16_as_ushort(__float2bfloat16(rintf(__fdiv_rn(xv.y, s))));
        u.z = __bfloat16_as_ushort(__float2bfloat16(rintf(__fdiv_rn(xv.z, s))));
        u.w = __bfloat16_as_ushort(__float2bfloat16(rintf(__fdiv_rn(xv.w, s))));
        qr[g] = u;
    }
}

// ============================================================================
// Kernel 2: split fp32 W into bf16 hi + lo planes (W ~= hi + lo, ~2^-17 rel)
// ============================================================================
__global__ void __launch_bounds__(256) wsplit_kernel(const float* __restrict__ w) {
    int i = blockIdx.x * 256 + threadIdx.x;   // float4 index over DOUT*DIN/4
    float4 wv = reinterpret_cast<const float4*>(w)[i];
    __nv_bfloat16 h0 = __float2bfloat16(wv.x);
    __nv_bfloat16 h1 = __float2bfloat16(wv.y);
    __nv_bfloat16 h2 = __float2bfloat16(wv.z);
    __nv_bfloat16 h3 = __float2bfloat16(wv.w);
    __nv_bfloat16 l0 = __float2bfloat16(wv.x - __bfloat162float(h0));
    __nv_bfloat16 l1 = __float2bfloat16(wv.y - __bfloat162float(h1));
    __nv_bfloat16 l2 = __float2bfloat16(wv.z - __bfloat162float(h2));
    __nv_bfloat16 l3 = __float2bfloat16(wv.w - __bfloat162float(h3));
    ushort4 uh, ul;
    uh.x = __bfloat16_as_ushort(h0); uh.y = __bfloat16_as_ushort(h1);
    uh.z = __bfloat16_as_ushort(h2); uh.w = __bfloat16_as_ushort(h3);
    ul.x = __bfloat16_as_ushort(l0); ul.y = __bfloat16_as_ushort(l1);
    ul.z = __bfloat16_as_ushort(l2); ul.w = __bfloat16_as_ushort(l3);
    reinterpret_cast<ushort4*>(g_w2)[i] = uh;
    reinterpret_cast<ushort4*>(g_w2)[i + ((size_t)DOUT * DIN) / 4] = ul;
}

// ============================================================================
// Kernel 3: pipelined HMMA GEMM (sm_103 non-"a" PTX only: cp.async + ldmatrix
//           + mma.sync.m16n8k16.bf16).  out[m][n] = ts[m]*sum_k q*(Whi+Wlo) + bias
// CTA tile 128x128, BK=64, 4 cp.async stages (48KB/stage), 8 warps 2(M)x4(N),
// warp tile 64x32, both W planes accumulated into the same fp32 registers.
// ============================================================================
#define BK        64
#define KITERS    (DIN / BK)
#define STAGES    4
#define STAGE_B   49152                 // 16KB A + 2*16KB B
#define SMEM_BYTES (STAGES * STAGE_B)
#define PLANE     ((size_t)DOUT * DIN)

__device__ __forceinline__ uint32_t smem_u32(const void* p) {
    uint32_t a;
    asm("{ .reg .u64 t; cvta.to.shared.u64 t, %1; cvt.u32.u64 %0, t; }" : "=r"(a) : "l"(p));
    return a;
}
__device__ __forceinline__ void cp16(uint32_t dst, const void* src) {
    asm volatile("cp.async.cg.shared.global [%0], [%1], 16;" :: "r"(dst), "l"(src));
}
#define CP_COMMIT() asm volatile("cp.async.commit_group;" ::: "memory")
#define CP_WAIT2()  asm volatile("cp.async.wait_group 2;" ::: "memory")

#define LDSM4(r, addr) \
    asm volatile("ldmatrix.sync.aligned.m8n8.x4.shared.b16 {%0,%1,%2,%3}, [%4];" \
        : "=r"((r)[0]), "=r"((r)[1]), "=r"((r)[2]), "=r"((r)[3]) : "r"(addr))

#define MMA16816(d, a, b0, b1) \
    asm volatile("mma.sync.aligned.m16n8k16.row.col.f32.bf16.bf16.f32 " \
        "{%0,%1,%2,%3}, {%4,%5,%6,%7}, {%8,%9}, {%0,%1,%2,%3};" \
        : "+f"((d)[0]), "+f"((d)[1]), "+f"((d)[2]), "+f"((d)[3]) \
        : "r"((a)[0]), "r"((a)[1]), "r"((a)[2]), "r"((a)[3]), "r"(b0), "r"(b1))

__global__ void __launch_bounds__(256, 1) gemm_kernel(const float* __restrict__ bias,
                                                      float* __restrict__ out) {
    extern __shared__ __align__(1024) char smem[];
    const uint32_t sb = smem_u32(smem);
    const int tid  = threadIdx.x;
    const int lane = tid & 31;
    const int wid  = tid >> 5;
    const int wm   = wid & 1;            // 2 warps along M
    const int wn   = wid >> 1;           // 4 warps along N
    const int m0   = blockIdx.y * 128;
    const int n0   = blockIdx.x * 128;

    // ---------- cp.async producer addressing (per thread: 12 x 16B) ----------
    // chunk layout: 128 rows x 8 chunks (16B) per 64-col bf16 row; 8-row XOR swizzle
    const int prow = tid >> 3;           // 0..31, +t*32
    const int pcol = tid & 7;
    const uint32_t dst0 = (uint32_t)prow * 128 + (uint32_t)((pcol ^ (prow & 7)) << 4);
    const unsigned short* qa = g_q  + (size_t)(m0 + prow) * DIN + pcol * 8;
    const unsigned short* wb = g_w2 + (size_t)(n0 + prow) * DIN + pcol * 8;

    // ---------- ldmatrix consumer addressing ----------
    const uint32_t sw   = (uint32_t)(lane & 7);
    const uint32_t ahi  = (uint32_t)((lane >> 4) & 1);       // A k-chunk half
    const uint32_t bkb  = (uint32_t)((lane >> 3) & 1);       // B k-chunk half
    uint32_t rA[4], rB[2];
#pragma unroll
    for (int mt = 0; mt < 4; ++mt)
        rA[mt] = (uint32_t)(wm * 64 + mt * 16 + (lane & 15)) * 128;
#pragma unroll
    for (int ntp = 0; ntp < 2; ++ntp)
        rB[ntp] = (uint32_t)(wn * 32 + ntp * 16 + ((lane >> 4) & 1) * 8 + (lane & 7)) * 128;

    float acc[4][4][4];
#pragma unroll
    for (int i = 0; i < 4; ++i)
#pragma unroll
        for (int j = 0; j < 4; ++j)
#pragma unroll
            for (int k = 0; k < 4; ++k) acc[i][j][k] = 0.f;

    // ---------- prologue: fill STAGES-1 stages ----------
#pragma unroll
    for (int s = 0; s < STAGES - 1; ++s) {
        uint32_t sbase = sb + s * STAGE_B;
        int koff = s * BK;
#pragma unroll
        for (int t = 0; t < 4; ++t) {
            cp16(sbase +         dst0 + t * 4096, qa + (size_t)t * 32 * DIN + koff);
            cp16(sbase + 16384 + dst0 + t * 4096, wb + (size_t)t * 32 * DIN + koff);
            cp16(sbase + 32768 + dst0 + t * 4096, wb + PLANE + (size_t)t * 32 * DIN + koff);
        }
        CP_COMMIT();
    }

    // ---------- main loop ----------
#pragma unroll 1
    for (int kt = 0; kt < KITERS; ++kt) {
        CP_WAIT2();
        __syncthreads();

        const uint32_t stA = sb + (kt % STAGES) * STAGE_B;
#pragma unroll
        for (int ks = 0; ks < 4; ++ks) {
            uint32_t a[4][4];
#pragma unroll
            for (int mt = 0; mt < 4; ++mt) {
                uint32_t addr = stA + rA[mt] + (((2u * ks + ahi) ^ sw) << 4);
                LDSM4(a[mt], addr);
            }
#pragma unroll
            for (int p = 0; p < 2; ++p) {
                uint32_t pb = stA + 16384 + p * 16384;
#pragma unroll
                for (int ntp = 0; ntp < 2; ++ntp) {
                    uint32_t b[4];
                    uint32_t addr = pb + rB[ntp] + (((2u * ks + bkb) ^ sw) << 4);
                    LDSM4(b, addr);
#pragma unroll
                    for (int mt = 0; mt < 4; ++mt) {
                        MMA16816(acc[mt][2 * ntp],     a[mt], b[0], b[1]);
                        MMA16816(acc[mt][2 * ntp + 1], a[mt], b[2], b[3]);
                    }
                }
            }
        }
        __syncthreads();

        int nk = kt + STAGES - 1;
        if (nk < KITERS) {
            uint32_t sbase = sb + (nk % STAGES) * STAGE_B;
            int koff = nk * BK;
#pragma unroll
            for (int t = 0; t < 4; ++t) {
                cp16(sbase +         dst0 + t * 4096, qa + (size_t)t * 32 * DIN + koff);
                cp16(sbase + 16384 + dst0 + t * 4096, wb + (size_t)t * 32 * DIN + koff);
                cp16(sbase + 32768 + dst0 + t * 4096, wb + PLANE + (size_t)t * 32 * DIN + koff);
            }
        }
        CP_COMMIT();
    }

    // ---------- epilogue: y = acc * ts[m] + bias[n] ----------
    const int mbase = m0 + wm * 64;
    const int nbase = n0 + wn * 32;
#pragma unroll
    for (int mt = 0; mt < 4; ++mt) {
        int r = mbase + mt * 16 + (lane >> 2);
        float s0 = g_ts[r];
        float s1 = g_ts[r + 8];
        float* o0 = out + (size_t)r * DOUT;
        float* o1 = o0 + (size_t)8 * DOUT;
#pragma unroll
        for (int nt = 0; nt < 4; ++nt) {
            int n = nbase + nt * 8 + (lane & 3) * 2;
            float2 bb = *reinterpret_cast<const float2*>(bias + n);
            float2 v0, v1;
            v0.x = acc[mt][nt][0] * s0 + bb.x;
            v0.y = acc[mt][nt][1] * s0 + bb.y;
            v1.x = acc[mt][nt][2] * s1 + bb.x;
            v1.y = acc[mt][nt][3] * s1 + bb.y;
            *reinterpret_cast<float2*>(o0 + n) = v0;
            *reinterpret_cast<float2*>(o1 + n) = v1;
        }
    }
}

// ============================================================================
// host launcher
// ============================================================================
extern "C" void kernel_launch(void* const* d_in, const int* in_sizes, int n_in,
                              void* d_out, int out_size) {
    const float* x    = (const float*)d_in[0];   // (B,S,DIN)
    const float* w    = (const float*)d_in[1];   // (DOUT,DIN)
    const float* bias = (const float*)d_in[2];   // (1,DOUT)
    const float* ss   = (const float*)d_in[3];   // (1,DIN)
    float* out = (float*)d_out;
    int T = in_sizes[0] / DIN;                   // 8192 tokens

    static bool attr_set = false;
    if (!attr_set) {
        cudaFuncSetAttribute(gemm_kernel, cudaFuncAttributeMaxDynamicSharedMemorySize,
                             SMEM_BYTES);
        attr_set = true;
    }

    prep_kernel<<<T, 128>>>(x, ss);
    wsplit_kernel<<<(DOUT * DIN / 4) / 256, 256>>>(w);
    dim3 grid(DOUT / 128, T / 128);
    gemm_kernel<<<grid, 256, SMEM_BYTES>>>(bias, out);
}